// round 1
// baseline (speedup 1.0000x reference)
#include <cuda_runtime.h>

// Shapes (fixed by the problem)
#define B_ 64
#define S_ 197
#define D_ 768
#define P_ 196
#define M_ (B_ * S_)   // 12608 = 197 * 64

// Scratch for v = x @ Wv + bv  (no cudaMalloc allowed -> __device__ global)
__device__ float g_v[(size_t)M_ * D_];

// ---------------------------------------------------------------------------
// GEMM: C[M_,768] = A[M_,768] @ W[768,768] + bias   (all fp32, row-major)
// BM=64 (197 tiles exactly), BN=128 (6 tiles exactly), BK=16 (48 steps exactly)
// 256 threads, each computes a 4(m) x 8(n) micro-tile.
// ---------------------------------------------------------------------------
#define BM 64
#define BN 128
#define BK 16

__global__ __launch_bounds__(256, 2) void gemm_bias_kernel(
    const float* __restrict__ A, const float* __restrict__ W,
    const float* __restrict__ bias, float* __restrict__ C)
{
    __shared__ float As[BK][BM];   // As[k][m]
    __shared__ float Bs[BK][BN];   // Bs[k][n]

    const int tid = threadIdx.x;
    const int m0 = blockIdx.y * BM;
    const int n0 = blockIdx.x * BN;

    // A-tile load map: 64 rows x 16 k = 1024 floats = 256 float4 (1 per thread)
    const int aRow = tid >> 2;          // 0..63
    const int aK   = (tid & 3) * 4;     // 0,4,8,12
    // B-tile load map: 16 k x 128 n = 2048 floats = 512 float4 (2 per thread)
    const int bK = tid >> 5;            // 0..7  (and bK+8)
    const int bN = (tid & 31) * 4;      // 0..124

    const int tm = (tid >> 4) * 4;      // 0..60
    const int tn = (tid & 15) * 8;      // 0..120

    float acc[4][8];
#pragma unroll
    for (int i = 0; i < 4; i++)
#pragma unroll
        for (int j = 0; j < 8; j++) acc[i][j] = 0.0f;

    const float* Aptr = A + (size_t)(m0 + aRow) * D_ + aK;
    const float* Wptr = W + n0 + bN;

    for (int k0 = 0; k0 < D_; k0 += BK) {
        float4 av = *(const float4*)(Aptr + k0);
        As[aK + 0][aRow] = av.x;
        As[aK + 1][aRow] = av.y;
        As[aK + 2][aRow] = av.z;
        As[aK + 3][aRow] = av.w;
        float4 b0 = *(const float4*)(Wptr + (size_t)(k0 + bK) * D_);
        float4 b1 = *(const float4*)(Wptr + (size_t)(k0 + bK + 8) * D_);
        *(float4*)&Bs[bK][bN]     = b0;
        *(float4*)&Bs[bK + 8][bN] = b1;
        __syncthreads();

#pragma unroll
        for (int k = 0; k < BK; k++) {
            float4 a4  = *(const float4*)&As[k][tm];
            float4 bb0 = *(const float4*)&Bs[k][tn];
            float4 bb1 = *(const float4*)&Bs[k][tn + 4];
            float ar[4] = {a4.x, a4.y, a4.z, a4.w};
            float br[8] = {bb0.x, bb0.y, bb0.z, bb0.w,
                           bb1.x, bb1.y, bb1.z, bb1.w};
#pragma unroll
            for (int i = 0; i < 4; i++)
#pragma unroll
                for (int j = 0; j < 8; j++)
                    acc[i][j] = fmaf(ar[i], br[j], acc[i][j]);
        }
        __syncthreads();
    }

#pragma unroll
    for (int i = 0; i < 4; i++) {
        float* crow = C + (size_t)(m0 + tm + i) * D_ + n0 + tn;
#pragma unroll
        for (int j = 0; j < 8; j += 4) {
            float4 r;
            r.x = acc[i][j + 0] + bias[n0 + tn + j + 0];
            r.y = acc[i][j + 1] + bias[n0 + tn + j + 1];
            r.z = acc[i][j + 2] + bias[n0 + tn + j + 2];
            r.w = acc[i][j + 3] + bias[n0 + tn + j + 3];
            *(float4*)(crow + j) = r;
        }
    }
}

// ---------------------------------------------------------------------------
// Sampling: one block per output row (b, s). s==0 -> ones (class token),
// else bilinear 4-point gather of v[b] rows. attn==1 so out = sampled v.
// ---------------------------------------------------------------------------
__device__ __forceinline__ int wrap197(int i)
{
    int r = i % S_;
    return (r < 0) ? r + S_ : r;
}

__global__ __launch_bounds__(192) void sample_kernel(
    const int* __restrict__ img_ids, const float* __restrict__ avgs,
    const float* __restrict__ stds, const float* __restrict__ noise,
    float* __restrict__ out)
{
    const int row = blockIdx.x;        // 0..M_-1
    const int b = row / S_;
    const int s = row - b * S_;
    const int t = threadIdx.x;         // 0..191, one float4 each (768/4 = 192)

    float4* orow = (float4*)(out + (size_t)row * D_);

    if (s == 0) {
        orow[t] = make_float4(1.0f, 1.0f, 1.0f, 1.0f);
        return;
    }
    const int p = s - 1;

    const int id = img_ids[b];
    const float nx = noise[(size_t)(b * 2 + 0) * P_ + p];
    const float ny = noise[(size_t)(b * 2 + 1) * P_ + p];
    const size_t gb = (size_t)id * 2 * P_;
    const float ax = avgs[gb + p];
    const float ay = avgs[gb + P_ + p];
    const float sx = stds[gb + p];
    const float sy = stds[gb + P_ + p];

    const float kx = (nx - ax) / sx;
    const float ky = (ny - ay) / sy;

    const float x1 = ceilf(kx),  x2 = floorf(kx);
    const float y1 = ceilf(ky),  y2 = floorf(ky);

    const float wx1 = 1.0f - fabsf(x1 - kx);
    const float wx2 = 1.0f - fabsf(x2 - kx);
    const float wy1 = 1.0f - fabsf(y1 - ky);
    const float wy2 = 1.0f - fabsf(y2 - ky);

    const float w11 = wx1 * wy1;
    const float w21 = wx2 * wy1;
    const float w12 = wx1 * wy2;
    const float w22 = wx2 * wy2;

    // idx = trunc(14*py + px) wrapped Python-style into [0, S)
    const int i11 = wrap197((int)(14.0f * y1 + x1));
    const int i21 = wrap197((int)(14.0f * y1 + x2));
    const int i12 = wrap197((int)(14.0f * y2 + x1));
    const int i22 = wrap197((int)(14.0f * y2 + x2));

    const float4* vb = (const float4*)g_v + (size_t)b * S_ * (D_ / 4);
    const float4 a = vb[(size_t)i11 * (D_ / 4) + t];
    const float4 c = vb[(size_t)i21 * (D_ / 4) + t];
    const float4 d = vb[(size_t)i12 * (D_ / 4) + t];
    const float4 e = vb[(size_t)i22 * (D_ / 4) + t];

    float4 r;
    r.x = w11 * a.x + w21 * c.x + w12 * d.x + w22 * e.x;
    r.y = w11 * a.y + w21 * c.y + w12 * d.y + w22 * e.y;
    r.z = w11 * a.z + w21 * c.z + w12 * d.z + w22 * e.z;
    r.w = w11 * a.w + w21 * c.w + w12 * d.w + w22 * e.w;
    orow[t] = r;
}

// ---------------------------------------------------------------------------
// Inputs (metadata order): 0:x 1:img_ids 2:mask 3:Wq 4:bq 5:Wk 6:bk
//                          7:Wv 8:bv 9:avgs 10:std_devs 11:noise
// q/k/Wq/Wk are dead code (softmax over singleton axis == 1): out = sampled v.
// ---------------------------------------------------------------------------
extern "C" void kernel_launch(void* const* d_in, const int* in_sizes, int n_in,
                              void* d_out, int out_size)
{
    const float* x       = (const float*)d_in[0];
    const int*   img_ids = (const int*)d_in[1];
    const float* Wv      = (const float*)d_in[7];
    const float* bv      = (const float*)d_in[8];
    const float* avgs    = (const float*)d_in[9];
    const float* stds    = (const float*)d_in[10];
    const float* noise   = (const float*)d_in[11];
    float* out = (float*)d_out;

    float* v = nullptr;
    cudaGetSymbolAddress((void**)&v, g_v);   // address query only; capture-safe

    dim3 grid(D_ / BN, M_ / BM);             // (6, 197) — exact tiling
    gemm_bias_kernel<<<grid, 256>>>(x, Wv, bv, v);
    sample_kernel<<<M_, 192>>>(img_ids, avgs, stds, noise, out);
}

// round 3
// speedup vs baseline: 3.5039x; 3.5039x over previous
#include <cuda_runtime.h>
#include <cstdint>

// Shapes (fixed by the problem)
#define B_ 64
#define S_ 197
#define D_ 768
#define P_ 196
#define M_ (B_ * S_)   // 12608

// Device scratch for v = x @ Wv + bv (no cudaMalloc allowed)
__device__ float g_v[(size_t)M_ * D_];

__device__ __forceinline__ uint32_t f2tf32(float x) {   // round-to-nearest tf32
    uint32_t r;
    asm("cvt.rna.tf32.f32 %0, %1;" : "=r"(r) : "f"(x));
    return r;
}

__device__ __forceinline__ void mma_tf32(float* d, const uint32_t* a, const uint32_t* b)
{
    asm volatile(
        "mma.sync.aligned.m16n8k8.row.col.f32.tf32.tf32.f32 "
        "{%0,%1,%2,%3}, {%4,%5,%6,%7}, {%8,%9}, {%0,%1,%2,%3};"
        : "+f"(d[0]), "+f"(d[1]), "+f"(d[2]), "+f"(d[3])
        : "r"(a[0]), "r"(a[1]), "r"(a[2]), "r"(a[3]), "r"(b[0]), "r"(b[1]));
}

// ---------------------------------------------------------------------------
// TF32 tensor-core GEMM: C[M_,768] = A[M_,768] @ W[768,768] + bias
// CTA tile 128x128, BK=16, 256 threads = 8 warps (2m x 4n), warp tile 64x32.
// Double-buffered smem, padded pitches for conflict-free fragment loads.
// ---------------------------------------------------------------------------
#define BK   16
#define NSTG 48            // 768 / 16
#define AP   20            // A smem pitch (floats): (20g+t)%32 distinct
#define BPitch 136         // B smem pitch (floats): (8k+g)%32 distinct

__global__ __launch_bounds__(256) void gemm_tf32(
    const float* __restrict__ A, const float* __restrict__ W,
    const float* __restrict__ bias, float* __restrict__ C)
{
    __shared__ __align__(16) uint32_t As[2][128][AP];     // [buf][m][k]
    __shared__ __align__(16) uint32_t Bs[2][BK][BPitch];  // [buf][k][n]

    const int tid  = threadIdx.x;
    const int wid  = tid >> 5;
    const int lane = tid & 31;
    const int g    = lane >> 2;       // 0..7
    const int t4   = lane & 3;        // 0..3
    const int wm   = wid & 1;         // warp m index (0..1) -> 64 rows
    const int wn   = wid >> 1;        // warp n index (0..3) -> 32 cols
    const int m0 = blockIdx.y * 128;
    const int n0 = blockIdx.x * 128;

    // global load maps (512 float4 per tile each, 2 per thread)
    const int aRow = tid >> 1;                 // 0..127
    const int aK   = (tid & 1) * 8;            // 0 or 8 (two float4)
    const int bRow0 = tid >> 5;                // 0..7 (and +8)
    const int bN    = (tid & 31) * 4;          // 0..124

    int aGrow = m0 + aRow; if (aGrow >= M_) aGrow = M_ - 1;
    const float* Ap = A + (size_t)aGrow * D_ + aK;
    const float* Wp = W + n0 + bN;

    float acc[4][4][4];
#pragma unroll
    for (int i = 0; i < 4; i++)
#pragma unroll
        for (int j = 0; j < 4; j++)
#pragma unroll
            for (int r = 0; r < 4; r++) acc[i][j][r] = 0.0f;

    // prologue: load stage 0
    float4 ra0, ra1, rb0, rb1;
    ra0 = *(const float4*)(Ap + 0);
    ra1 = *(const float4*)(Ap + 4);
    rb0 = *(const float4*)(Wp + (size_t)(bRow0)     * D_);
    rb1 = *(const float4*)(Wp + (size_t)(bRow0 + 8) * D_);
    {
        uint4 t0 = make_uint4(f2tf32(ra0.x), f2tf32(ra0.y), f2tf32(ra0.z), f2tf32(ra0.w));
        uint4 t1 = make_uint4(f2tf32(ra1.x), f2tf32(ra1.y), f2tf32(ra1.z), f2tf32(ra1.w));
        *(uint4*)&As[0][aRow][aK]     = t0;
        *(uint4*)&As[0][aRow][aK + 4] = t1;
        uint4 u0 = make_uint4(f2tf32(rb0.x), f2tf32(rb0.y), f2tf32(rb0.z), f2tf32(rb0.w));
        uint4 u1 = make_uint4(f2tf32(rb1.x), f2tf32(rb1.y), f2tf32(rb1.z), f2tf32(rb1.w));
        *(uint4*)&Bs[0][bRow0][bN]     = u0;
        *(uint4*)&Bs[0][bRow0 + 8][bN] = u1;
    }
    __syncthreads();

    for (int s = 0; s < NSTG; s++) {
        const int buf = s & 1;
        // issue next stage's global loads early (hide latency under compute)
        if (s + 1 < NSTG) {
            const int k0 = (s + 1) * BK;
            ra0 = *(const float4*)(Ap + k0);
            ra1 = *(const float4*)(Ap + k0 + 4);
            rb0 = *(const float4*)(Wp + (size_t)(k0 + bRow0)     * D_);
            rb1 = *(const float4*)(Wp + (size_t)(k0 + bRow0 + 8) * D_);
        }

        // compute on buf
        const uint32_t* Asb = &As[buf][wm * 64][0];
        const uint32_t* Bsb = &Bs[buf][0][wn * 32];
#pragma unroll
        for (int kk = 0; kk < BK; kk += 8) {
            uint32_t a[4][4], b[4][2];
#pragma unroll
            for (int fm = 0; fm < 4; fm++) {
                const uint32_t* p = Asb + (fm * 16 + g) * AP + kk + t4;
                a[fm][0] = p[0];
                a[fm][1] = p[8 * AP];
                a[fm][2] = p[4];
                a[fm][3] = p[8 * AP + 4];
            }
#pragma unroll
            for (int fn = 0; fn < 4; fn++) {
                const uint32_t* p = Bsb + (kk + t4) * BPitch + fn * 8 + g;
                b[fn][0] = p[0];
                b[fn][1] = p[4 * BPitch];
            }
#pragma unroll
            for (int fm = 0; fm < 4; fm++)
#pragma unroll
                for (int fn = 0; fn < 4; fn++)
                    mma_tf32(acc[fm][fn], a[fm], b[fn]);
        }

        if (s + 1 < NSTG) {
            const int nbuf = buf ^ 1;
            __syncthreads();   // everyone done reading nbuf (stage s-1)
            uint4 t0 = make_uint4(f2tf32(ra0.x), f2tf32(ra0.y), f2tf32(ra0.z), f2tf32(ra0.w));
            uint4 t1 = make_uint4(f2tf32(ra1.x), f2tf32(ra1.y), f2tf32(ra1.z), f2tf32(ra1.w));
            *(uint4*)&As[nbuf][aRow][aK]     = t0;
            *(uint4*)&As[nbuf][aRow][aK + 4] = t1;
            uint4 u0 = make_uint4(f2tf32(rb0.x), f2tf32(rb0.y), f2tf32(rb0.z), f2tf32(rb0.w));
            uint4 u1 = make_uint4(f2tf32(rb1.x), f2tf32(rb1.y), f2tf32(rb1.z), f2tf32(rb1.w));
            *(uint4*)&Bs[nbuf][bRow0][bN]     = u0;
            *(uint4*)&Bs[nbuf][bRow0 + 8][bN] = u1;
            __syncthreads();
        }
    }

    // epilogue: write acc + bias
#pragma unroll
    for (int fn = 0; fn < 4; fn++) {
        const int col = n0 + wn * 32 + fn * 8 + t4 * 2;
        const float b0 = bias[col];
        const float b1 = bias[col + 1];
#pragma unroll
        for (int fm = 0; fm < 4; fm++) {
            const int row0 = m0 + wm * 64 + fm * 16 + g;
            const int row1 = row0 + 8;
            if (row0 < M_) {
                float2 o = make_float2(acc[fm][fn][0] + b0, acc[fm][fn][1] + b1);
                *(float2*)(C + (size_t)row0 * D_ + col) = o;
            }
            if (row1 < M_) {
                float2 o = make_float2(acc[fm][fn][2] + b0, acc[fm][fn][3] + b1);
                *(float2*)(C + (size_t)row1 * D_ + col) = o;
            }
        }
    }
}

// ---------------------------------------------------------------------------
// Sampling: out = bilinear 4-point gather of v rows; row 0 of each batch = 1.
// (softmax over singleton axis == 1 -> attn is identically 1; q/k are dead)
// ---------------------------------------------------------------------------
__device__ __forceinline__ int wrap197(int i)
{
    int r = i % S_;
    return (r < 0) ? r + S_ : r;
}

__global__ __launch_bounds__(192) void sample_kernel(
    const int* __restrict__ img_ids, const float* __restrict__ avgs,
    const float* __restrict__ stds, const float* __restrict__ noise,
    float* __restrict__ out)
{
    const int row = blockIdx.x;
    const int b = row / S_;
    const int s = row - b * S_;
    const int t = threadIdx.x;

    float4* orow = (float4*)(out + (size_t)row * D_);
    if (s == 0) {
        orow[t] = make_float4(1.0f, 1.0f, 1.0f, 1.0f);
        return;
    }
    const int p = s - 1;
    const int id = img_ids[b];
    const float nx = noise[(size_t)(b * 2 + 0) * P_ + p];
    const float ny = noise[(size_t)(b * 2 + 1) * P_ + p];
    const size_t gb = (size_t)id * 2 * P_;
    const float ax = avgs[gb + p],  ay = avgs[gb + P_ + p];
    const float sx = stds[gb + p],  sy = stds[gb + P_ + p];

    const float kx = (nx - ax) / sx;
    const float ky = (ny - ay) / sy;
    const float x1 = ceilf(kx),  x2 = floorf(kx);
    const float y1 = ceilf(ky),  y2 = floorf(ky);
    const float wx1 = 1.0f - fabsf(x1 - kx);
    const float wx2 = 1.0f - fabsf(x2 - kx);
    const float wy1 = 1.0f - fabsf(y1 - ky);
    const float wy2 = 1.0f - fabsf(y2 - ky);
    const float w11 = wx1 * wy1, w21 = wx2 * wy1;
    const float w12 = wx1 * wy2, w22 = wx2 * wy2;

    const int i11 = wrap197((int)(14.0f * y1 + x1));
    const int i21 = wrap197((int)(14.0f * y1 + x2));
    const int i12 = wrap197((int)(14.0f * y2 + x1));
    const int i22 = wrap197((int)(14.0f * y2 + x2));

    const float4* vb = (const float4*)g_v + (size_t)b * S_ * (D_ / 4);
    const float4 a = vb[(size_t)i11 * (D_ / 4) + t];
    const float4 c = vb[(size_t)i21 * (D_ / 4) + t];
    const float4 d = vb[(size_t)i12 * (D_ / 4) + t];
    const float4 e = vb[(size_t)i22 * (D_ / 4) + t];

    float4 r;
    r.x = w11 * a.x + w21 * c.x + w12 * d.x + w22 * e.x;
    r.y = w11 * a.y + w21 * c.y + w12 * d.y + w22 * e.y;
    r.z = w11 * a.z + w21 * c.z + w12 * d.z + w22 * e.z;
    r.w = w11 * a.w + w21 * c.w + w12 * d.w + w22 * e.w;
    orow[t] = r;
}

// ---------------------------------------------------------------------------
// Inputs (metadata order): 0:x 1:img_ids 2:mask 3:Wq 4:bq 5:Wk 6:bk
//                          7:Wv 8:bv 9:avgs 10:std_devs 11:noise
// ---------------------------------------------------------------------------
extern "C" void kernel_launch(void* const* d_in, const int* in_sizes, int n_in,
                              void* d_out, int out_size)
{
    const float* x       = (const float*)d_in[0];
    const int*   img_ids = (const int*)d_in[1];
    const float* Wv      = (const float*)d_in[7];
    const float* bv      = (const float*)d_in[8];
    const float* avgs    = (const float*)d_in[9];
    const float* stds    = (const float*)d_in[10];
    const float* noise   = (const float*)d_in[11];
    float* out = (float*)d_out;

    float* v = nullptr;
    cudaGetSymbolAddress((void**)&v, g_v);

    gemm_tf32<<<dim3(6, 99), 256>>>(x, Wv, bv, v);
    sample_kernel<<<M_, 192>>>(img_ids, avgs, stds, noise, out);
}

// round 4
// speedup vs baseline: 3.9393x; 1.1243x over previous
#include <cuda_runtime.h>
#include <cstdint>

// Shapes (fixed by the problem)
#define B_ 64
#define S_ 197
#define D_ 768
#define P_ 196
#define M_ (B_ * S_)   // 12608

// Device scratch (no cudaMalloc allowed)
__device__ float    g_v[(size_t)M_ * D_];    // v = x @ Wv + bv
__device__ uint32_t g_xr[(size_t)M_ * D_];   // x rounded to tf32 (rna)
__device__ uint32_t g_wr[(size_t)D_ * D_];   // Wv rounded to tf32 (rna)

__device__ __forceinline__ uint32_t f2tf32(float x) {   // round-to-nearest tf32
    uint32_t r;
    asm("cvt.rna.tf32.f32 %0, %1;" : "=r"(r) : "f"(x));
    return r;
}
__device__ __forceinline__ uint32_t smem_u32(const void* p) {
    uint32_t a;
    asm("{ .reg .u64 t; cvta.to.shared.u64 t, %1; cvt.u32.u64 %0, t; }"
        : "=r"(a) : "l"(p));
    return a;
}
__device__ __forceinline__ void cp_async16(uint32_t dst, const void* src) {
    asm volatile("cp.async.cg.shared.global [%0], [%1], 16;"
                 :: "r"(dst), "l"(src));
}
#define CP_COMMIT() asm volatile("cp.async.commit_group;" ::: "memory")
#define CP_WAIT(n)  asm volatile("cp.async.wait_group %0;" :: "n"(n) : "memory")

__device__ __forceinline__ void mma_tf32(float* d, const uint32_t* a, const uint32_t* b)
{
    asm volatile(
        "mma.sync.aligned.m16n8k8.row.col.f32.tf32.tf32.f32 "
        "{%0,%1,%2,%3}, {%4,%5,%6,%7}, {%8,%9}, {%0,%1,%2,%3};"
        : "+f"(d[0]), "+f"(d[1]), "+f"(d[2]), "+f"(d[3])
        : "r"(a[0]), "r"(a[1]), "r"(a[2]), "r"(a[3]), "r"(b[0]), "r"(b[1]));
}

// ---------------------------------------------------------------------------
// Pre-round fp32 -> tf32 (rna).  Vectorized float4 grid-stride-free map.
// ---------------------------------------------------------------------------
__global__ __launch_bounds__(256) void round_tf32(const float* __restrict__ in,
                                                  uint32_t* __restrict__ out, int n4)
{
    const int i = blockIdx.x * 256 + threadIdx.x;
    if (i < n4) {
        float4 v = ((const float4*)in)[i];
        uint4 r = make_uint4(f2tf32(v.x), f2tf32(v.y), f2tf32(v.z), f2tf32(v.w));
        ((uint4*)out)[i] = r;
    }
}

// ---------------------------------------------------------------------------
// TF32 tensor GEMM: C[M_,768] = A @ W + bias, operands pre-rounded to tf32.
// CTA 128x128, BK=16, 4-stage cp.async pipeline, 8 warps (2m x 4n), 64x32
// warp tiles, m16n8k8 fragments. XOR-swizzled smem (A conflict-free).
// ---------------------------------------------------------------------------
#define BK     16
#define NSTG   48          // 768/16
#define STAGES 4
#define A_ST   8192        // 128*16*4 bytes per stage
#define B_ST   8192        // 16*128*4 bytes per stage
#define SMEM_TOTAL (STAGES * (A_ST + B_ST))   // 64 KB

__global__ __launch_bounds__(256, 2) void gemm_tf32(
    const uint32_t* __restrict__ A, const uint32_t* __restrict__ W,
    const float* __restrict__ bias, float* __restrict__ C)
{
    extern __shared__ char smem[];
    const uint32_t sb = smem_u32(smem);

    const int tid  = threadIdx.x;
    const int wid  = tid >> 5;
    const int lane = tid & 31;
    const int g    = lane >> 2;       // 0..7
    const int t4   = lane & 3;        // 0..3
    const int wm   = wid & 1;         // 2 warp rows  -> 64 m each
    const int wn   = wid >> 1;        // 4 warp cols  -> 32 n each
    const int m0 = blockIdx.y * 128;
    const int n0 = blockIdx.x * 128;

    // cp.async chunk maps (512 16B-chunks per tile; 2 per thread each)
    const int aRow0 = tid >> 2;            // chunk id = tid       -> row
    const int aC0   = tid & 3;
    const int aRow1 = (tid + 256) >> 2;
    const int aC1   = (tid + 256) & 3;
    const int bRow0 = tid >> 5;            // 0..7
    const int bC0   = tid & 31;
    const int bRow1 = (tid + 256) >> 5;    // 8..15
    const int bC1   = bC0;

    int ga0 = m0 + aRow0; if (ga0 >= M_) ga0 = M_ - 1;
    int ga1 = m0 + aRow1; if (ga1 >= M_) ga1 = M_ - 1;
    const uint32_t* Ap0 = A + (size_t)ga0 * D_ + aC0 * 4;
    const uint32_t* Ap1 = A + (size_t)ga1 * D_ + aC1 * 4;
    const uint32_t* Wp0 = W + n0 + bC0 * 4;   // row added per stage

    const uint32_t aDst0 = sb + aRow0 * 64 + ((aC0 ^ ((aRow0 >> 1) & 3)) << 4);
    const uint32_t aDst1 = sb + aRow1 * 64 + ((aC1 ^ ((aRow1 >> 1) & 3)) << 4);
    const uint32_t bDst0 = sb + STAGES * A_ST + (bRow0 << 9) + ((bC0 ^ (bRow0 & 3)) << 4);
    const uint32_t bDst1 = sb + STAGES * A_ST + (bRow1 << 9) + ((bC1 ^ (bRow1 & 3)) << 4);

    float acc[4][4][4];
#pragma unroll
    for (int i = 0; i < 4; i++)
#pragma unroll
        for (int j = 0; j < 4; j++)
#pragma unroll
            for (int r = 0; r < 4; r++) acc[i][j][r] = 0.0f;

    // prologue: stages 0..STAGES-2
#pragma unroll
    for (int s = 0; s < STAGES - 1; s++) {
        const int k0 = s * BK;
        const uint32_t so = (uint32_t)(s * A_ST);
        cp_async16(aDst0 + so, Ap0 + k0);
        cp_async16(aDst1 + so, Ap1 + k0);
        cp_async16(bDst0 + so, Wp0 + (size_t)(k0 + bRow0) * D_);
        cp_async16(bDst1 + so, Wp0 + (size_t)(k0 + bRow1) * D_);
        CP_COMMIT();
    }

    for (int s = 0; s < NSTG; s++) {
        // issue stage s+STAGES-1
        const int sl = s + STAGES - 1;
        if (sl < NSTG) {
            const int k0 = sl * BK;
            const uint32_t so = (uint32_t)((sl & (STAGES - 1)) * A_ST);
            cp_async16(aDst0 + so, Ap0 + k0);
            cp_async16(aDst1 + so, Ap1 + k0);
            cp_async16(bDst0 + so, Wp0 + (size_t)(k0 + bRow0) * D_);
            cp_async16(bDst1 + so, Wp0 + (size_t)(k0 + bRow1) * D_);
        }
        CP_COMMIT();
        CP_WAIT(STAGES - 1);
        __syncthreads();

        const char* Ab = smem + (s & (STAGES - 1)) * A_ST;
        const char* Bb = smem + STAGES * A_ST + (s & (STAGES - 1)) * B_ST;
#pragma unroll
        for (int kk = 0; kk < BK; kk += 8) {
            uint32_t a[4][4], b[4][2];
            const int kw0 = kk + t4;          // low k word
            const int kw1 = kk + t4 + 4;      // high k word
#pragma unroll
            for (int fm = 0; fm < 4; fm++) {
                const int row = wm * 64 + fm * 16 + g;
                const int sel = (row >> 1) & 3;
                const char* base0 = Ab + row * 64;
                const char* base1 = Ab + (row + 8) * 64;   // same sel
                const uint32_t o0 = (uint32_t)((((kw0 >> 2) ^ sel) << 4) + (kw0 & 3) * 4);
                const uint32_t o1 = (uint32_t)((((kw1 >> 2) ^ sel) << 4) + (kw1 & 3) * 4);
                a[fm][0] = *(const uint32_t*)(base0 + o0);
                a[fm][1] = *(const uint32_t*)(base1 + o0);
                a[fm][2] = *(const uint32_t*)(base0 + o1);
                a[fm][3] = *(const uint32_t*)(base1 + o1);
            }
#pragma unroll
            for (int fn = 0; fn < 4; fn++) {
                const int n = wn * 32 + fn * 8 + g;
                const uint32_t no = (uint32_t)((((n >> 2) ^ (kw0 & 3)) << 4) + (n & 3) * 4);
                b[fn][0] = *(const uint32_t*)(Bb + kw0 * 512 + no);
                b[fn][1] = *(const uint32_t*)(Bb + kw1 * 512 + no);  // (kw1&3)==(kw0&3)
            }
#pragma unroll
            for (int fm = 0; fm < 4; fm++)
#pragma unroll
                for (int fn = 0; fn < 4; fn++)
                    mma_tf32(acc[fm][fn], a[fm], b[fn]);
        }
        __syncthreads();
    }

    // epilogue: acc + bias -> C
#pragma unroll
    for (int fn = 0; fn < 4; fn++) {
        const int col = n0 + wn * 32 + fn * 8 + t4 * 2;
        const float b0 = bias[col];
        const float b1 = bias[col + 1];
#pragma unroll
        for (int fm = 0; fm < 4; fm++) {
            const int row0 = m0 + wm * 64 + fm * 16 + g;
            const int row1 = row0 + 8;
            if (row0 < M_) {
                float2 o = make_float2(acc[fm][fn][0] + b0, acc[fm][fn][1] + b1);
                *(float2*)(C + (size_t)row0 * D_ + col) = o;
            }
            if (row1 < M_) {
                float2 o = make_float2(acc[fm][fn][2] + b0, acc[fm][fn][3] + b1);
                *(float2*)(C + (size_t)row1 * D_ + col) = o;
            }
        }
    }
}

// ---------------------------------------------------------------------------
// Sampling: out = bilinear 4-point gather of v rows; row 0 of each batch = 1.
// (softmax over singleton axis == 1 -> attn identically 1; q/k dead code)
// ---------------------------------------------------------------------------
__device__ __forceinline__ int wrap197(int i)
{
    int r = i % S_;
    return (r < 0) ? r + S_ : r;
}

__global__ __launch_bounds__(192) void sample_kernel(
    const int* __restrict__ img_ids, const float* __restrict__ avgs,
    const float* __restrict__ stds, const float* __restrict__ noise,
    float* __restrict__ out)
{
    const int row = blockIdx.x;
    const int b = row / S_;
    const int s = row - b * S_;
    const int t = threadIdx.x;

    float4* orow = (float4*)(out + (size_t)row * D_);
    if (s == 0) {
        orow[t] = make_float4(1.0f, 1.0f, 1.0f, 1.0f);
        return;
    }
    const int p = s - 1;
    const int id = img_ids[b];
    const float nx = noise[(size_t)(b * 2 + 0) * P_ + p];
    const float ny = noise[(size_t)(b * 2 + 1) * P_ + p];
    const size_t gb = (size_t)id * 2 * P_;
    const float ax = avgs[gb + p],  ay = avgs[gb + P_ + p];
    const float sx = stds[gb + p],  sy = stds[gb + P_ + p];

    const float kx = (nx - ax) / sx;
    const float ky = (ny - ay) / sy;
    const float x1 = ceilf(kx),  x2 = floorf(kx);
    const float y1 = ceilf(ky),  y2 = floorf(ky);
    const float wx1 = 1.0f - fabsf(x1 - kx);
    const float wx2 = 1.0f - fabsf(x2 - kx);
    const float wy1 = 1.0f - fabsf(y1 - ky);
    const float wy2 = 1.0f - fabsf(y2 - ky);
    const float w11 = wx1 * wy1, w21 = wx2 * wy1;
    const float w12 = wx1 * wy2, w22 = wx2 * wy2;

    const int i11 = wrap197((int)(14.0f * y1 + x1));
    const int i21 = wrap197((int)(14.0f * y1 + x2));
    const int i12 = wrap197((int)(14.0f * y2 + x1));
    const int i22 = wrap197((int)(14.0f * y2 + x2));

    const float4* vb = (const float4*)g_v + (size_t)b * S_ * (D_ / 4);
    const float4 a = vb[(size_t)i11 * (D_ / 4) + t];
    const float4 c = vb[(size_t)i21 * (D_ / 4) + t];
    const float4 d = vb[(size_t)i12 * (D_ / 4) + t];
    const float4 e = vb[(size_t)i22 * (D_ / 4) + t];

    float4 r;
    r.x = w11 * a.x + w21 * c.x + w12 * d.x + w22 * e.x;
    r.y = w11 * a.y + w21 * c.y + w12 * d.y + w22 * e.y;
    r.z = w11 * a.z + w21 * c.z + w12 * d.z + w22 * e.z;
    r.w = w11 * a.w + w21 * c.w + w12 * d.w + w22 * e.w;
    orow[t] = r;
}

// ---------------------------------------------------------------------------
// Inputs (metadata order): 0:x 1:img_ids 2:mask 3:Wq 4:bq 5:Wk 6:bk
//                          7:Wv 8:bv 9:avgs 10:std_devs 11:noise
// ---------------------------------------------------------------------------
extern "C" void kernel_launch(void* const* d_in, const int* in_sizes, int n_in,
                              void* d_out, int out_size)
{
    const float* x       = (const float*)d_in[0];
    const int*   img_ids = (const int*)d_in[1];
    const float* Wv      = (const float*)d_in[7];
    const float* bv      = (const float*)d_in[8];
    const float* avgs    = (const float*)d_in[9];
    const float* stds    = (const float*)d_in[10];
    const float* noise   = (const float*)d_in[11];
    float* out = (float*)d_out;

    float*    v  = nullptr;
    uint32_t* xr = nullptr;
    uint32_t* wr = nullptr;
    cudaGetSymbolAddress((void**)&v,  g_v);
    cudaGetSymbolAddress((void**)&xr, g_xr);
    cudaGetSymbolAddress((void**)&wr, g_wr);

    cudaFuncSetAttribute(gemm_tf32, cudaFuncAttributeMaxDynamicSharedMemorySize,
                         SMEM_TOTAL);

    const int nx4 = (M_ * D_) / 4;   // 2,420,736
    const int nw4 = (D_ * D_) / 4;   // 147,456
    round_tf32<<<(nx4 + 255) / 256, 256>>>(x, xr, nx4);
    round_tf32<<<(nw4 + 255) / 256, 256>>>(Wv, wr, nw4);
    gemm_tf32<<<dim3(6, 99), 256, SMEM_TOTAL>>>(xr, wr, bv, v);
    sample_kernel<<<M_, 192>>>(img_ids, avgs, stds, noise, out);
}

// round 5
// speedup vs baseline: 6.6408x; 1.6858x over previous
#include <cuda_runtime.h>
#include <cuda_fp16.h>
#include <cstdint>

// Shapes (fixed by the problem)
#define B_ 64
#define S_ 197
#define D_ 768
#define P_ 196
#define M_ (B_ * S_)   // 12608

// Device scratch (no cudaMalloc allowed)
__device__ __half g_xs[(size_t)M_ * D_];    // weighted-gathered x, fp16
__device__ __half g_wt[(size_t)D_ * D_];    // Wv^T in fp16: g_wt[n][k]
__device__ float  g_ws[M_];                 // per-row weight sum

__device__ __forceinline__ uint32_t smem_u32(const void* p) {
    uint32_t a;
    asm("{ .reg .u64 t; cvta.to.shared.u64 t, %1; cvt.u32.u64 %0, t; }"
        : "=r"(a) : "l"(p));
    return a;
}
__device__ __forceinline__ void cp_async16(uint32_t dst, const void* src) {
    asm volatile("cp.async.cg.shared.global [%0], [%1], 16;"
                 :: "r"(dst), "l"(src));
}
#define CP_COMMIT() asm volatile("cp.async.commit_group;" ::: "memory")
#define CP_WAIT(n)  asm volatile("cp.async.wait_group %0;" :: "n"(n) : "memory")

__device__ __forceinline__ void mma_f16(float* d, const uint32_t* a, const uint32_t* b)
{
    asm volatile(
        "mma.sync.aligned.m16n8k16.row.col.f32.f16.f16.f32 "
        "{%0,%1,%2,%3}, {%4,%5,%6,%7}, {%8,%9}, {%0,%1,%2,%3};"
        : "+f"(d[0]), "+f"(d[1]), "+f"(d[2]), "+f"(d[3])
        : "r"(a[0]), "r"(a[1]), "r"(a[2]), "r"(a[3]), "r"(b[0]), "r"(b[1]));
}

// ---------------------------------------------------------------------------
// Wt[n][k] = (half) W[k][n]   (transpose + convert, rne)
// ---------------------------------------------------------------------------
__global__ __launch_bounds__(256) void transpose_half(const float* __restrict__ W,
                                                      __half* __restrict__ Wt)
{
    __shared__ float tile[32][33];
    const int tx = threadIdx.x, ty = threadIdx.y;   // 32 x 8
    int x = blockIdx.x * 32 + tx;
    int y = blockIdx.y * 32 + ty;
#pragma unroll
    for (int i = 0; i < 32; i += 8)
        tile[ty + i][tx] = W[(size_t)(y + i) * D_ + x];
    __syncthreads();
    x = blockIdx.y * 32 + tx;
    y = blockIdx.x * 32 + ty;
#pragma unroll
    for (int i = 0; i < 32; i += 8)
        Wt[(size_t)(y + i) * D_ + x] = __float2half_rn(tile[tx][ty + i]);
}

// ---------------------------------------------------------------------------
// Pre-gather: xs[b,s] = w11*x[b,i11] + w21*x[b,i21] + w12*x[b,i12] + w22*x[b,i22]
// (fp32 sum, single rne round to fp16).  Also stores wsum per row.
// Row s==0 (class token): xs=0, wsum=0 (epilogue writes 1.0 directly).
// ---------------------------------------------------------------------------
__device__ __forceinline__ int wrap197(int i)
{
    int r = i % S_;
    return (r < 0) ? r + S_ : r;
}

__global__ __launch_bounds__(192) void gather_x(
    const float* __restrict__ x, const int* __restrict__ img_ids,
    const float* __restrict__ avgs, const float* __restrict__ stds,
    const float* __restrict__ noise, __half* __restrict__ xs,
    float* __restrict__ wsum)
{
    const int row = blockIdx.x;
    const int b = row / S_;
    const int s = row - b * S_;
    const int t = threadIdx.x;      // 0..191, 4 elements each

    uint2* orow = (uint2*)(xs + (size_t)row * D_) + t;

    if (s == 0) {
        *orow = make_uint2(0u, 0u);
        if (t == 0) wsum[row] = 0.0f;
        return;
    }
    const int p = s - 1;
    const int id = img_ids[b];
    const float nx = noise[(size_t)(b * 2 + 0) * P_ + p];
    const float ny = noise[(size_t)(b * 2 + 1) * P_ + p];
    const size_t gb = (size_t)id * 2 * P_;
    const float ax = avgs[gb + p],  ay = avgs[gb + P_ + p];
    const float sx = stds[gb + p],  sy = stds[gb + P_ + p];

    const float kx = (nx - ax) / sx;
    const float ky = (ny - ay) / sy;
    const float x1 = ceilf(kx),  x2 = floorf(kx);
    const float y1 = ceilf(ky),  y2 = floorf(ky);
    const float wx1 = 1.0f - fabsf(x1 - kx);
    const float wx2 = 1.0f - fabsf(x2 - kx);
    const float wy1 = 1.0f - fabsf(y1 - ky);
    const float wy2 = 1.0f - fabsf(y2 - ky);
    const float w11 = wx1 * wy1, w21 = wx2 * wy1;
    const float w12 = wx1 * wy2, w22 = wx2 * wy2;

    const int i11 = wrap197((int)(14.0f * y1 + x1));
    const int i21 = wrap197((int)(14.0f * y1 + x2));
    const int i12 = wrap197((int)(14.0f * y2 + x1));
    const int i22 = wrap197((int)(14.0f * y2 + x2));

    const float4* xb = (const float4*)x + (size_t)b * S_ * (D_ / 4);
    const float4 a = xb[(size_t)i11 * (D_ / 4) + t];
    const float4 c = xb[(size_t)i21 * (D_ / 4) + t];
    const float4 d = xb[(size_t)i12 * (D_ / 4) + t];
    const float4 e = xb[(size_t)i22 * (D_ / 4) + t];

    float4 r;
    r.x = w11 * a.x + w21 * c.x + w12 * d.x + w22 * e.x;
    r.y = w11 * a.y + w21 * c.y + w12 * d.y + w22 * e.y;
    r.z = w11 * a.z + w21 * c.z + w12 * d.z + w22 * e.z;
    r.w = w11 * a.w + w21 * c.w + w12 * d.w + w22 * e.w;

    __half2 h0 = __floats2half2_rn(r.x, r.y);
    __half2 h1 = __floats2half2_rn(r.z, r.w);
    uint2 o;
    o.x = *(uint32_t*)&h0;
    o.y = *(uint32_t*)&h1;
    *orow = o;

    if (t == 0) wsum[row] = w11 + w21 + w12 + w22;
}

// ---------------------------------------------------------------------------
// FP16 tensor GEMM: out[M_,768] = xs @ Wt^T + wsum*bias (cls rows = 1.0)
// CTA 128x128, BK=32, 4-stage cp.async, 8 warps (2m x 4n), 64x32 warp tiles,
// m16n8k16 fragments. 80B row pitch -> conflict-free fragment LDS.
// ---------------------------------------------------------------------------
#define BK     32
#define NSTG   24          // 768/32
#define STAGES 4
#define ROWB   80          // bytes per smem row (64 data + 16 pad)
#define TILE_B (128 * ROWB)            // 10240
#define STAGE_B (2 * TILE_B)           // 20480 (A then B)
#define SMEM_TOTAL (STAGES * STAGE_B)  // 81920

__global__ __launch_bounds__(256, 2) void gemm_f16(
    const __half* __restrict__ A, const __half* __restrict__ Bt,
    const float* __restrict__ bias, const float* __restrict__ wsum,
    float* __restrict__ C)
{
    extern __shared__ char smem[];
    const uint32_t sb = smem_u32(smem);

    const int tid  = threadIdx.x;
    const int wid  = tid >> 5;
    const int lane = tid & 31;
    const int g    = lane >> 2;       // 0..7
    const int t4   = lane & 3;        // 0..3
    const int wm   = wid & 1;         // 2 warp rows -> 64 m each
    const int wn   = wid >> 1;        // 4 warp cols -> 32 n each
    const int m0 = blockIdx.y * 128;
    const int n0 = blockIdx.x * 128;

    // cp.async maps: 512 16B chunks per tile, 2 per thread each tile
    const int r0 = tid >> 2,        c0 = tid & 3;
    const int r1 = (tid + 256) >> 2, c1 = (tid + 256) & 3;

    int ga0 = m0 + r0; if (ga0 >= M_) ga0 = M_ - 1;
    int ga1 = m0 + r1; if (ga1 >= M_) ga1 = M_ - 1;
    const __half* Ap0 = A + (size_t)ga0 * D_ + c0 * 8;
    const __half* Ap1 = A + (size_t)ga1 * D_ + c1 * 8;
    const __half* Bp0 = Bt + (size_t)(n0 + r0) * D_ + c0 * 8;
    const __half* Bp1 = Bt + (size_t)(n0 + r1) * D_ + c1 * 8;

    const uint32_t aDst0 = sb + (uint32_t)(r0 * ROWB + c0 * 16);
    const uint32_t aDst1 = sb + (uint32_t)(r1 * ROWB + c1 * 16);
    const uint32_t bDst0 = aDst0 + TILE_B;
    const uint32_t bDst1 = aDst1 + TILE_B;

    float acc[4][4][4];
#pragma unroll
    for (int i = 0; i < 4; i++)
#pragma unroll
        for (int j = 0; j < 4; j++)
#pragma unroll
            for (int r = 0; r < 4; r++) acc[i][j][r] = 0.0f;

    // prologue
#pragma unroll
    for (int s = 0; s < STAGES - 1; s++) {
        const int k0 = s * BK;
        const uint32_t so = (uint32_t)(s * STAGE_B);
        cp_async16(aDst0 + so, Ap0 + k0);
        cp_async16(aDst1 + so, Ap1 + k0);
        cp_async16(bDst0 + so, Bp0 + k0);
        cp_async16(bDst1 + so, Bp1 + k0);
        CP_COMMIT();
    }

    for (int s = 0; s < NSTG; s++) {
        const int sl = s + STAGES - 1;
        if (sl < NSTG) {
            const int k0 = sl * BK;
            const uint32_t so = (uint32_t)((sl & (STAGES - 1)) * STAGE_B);
            cp_async16(aDst0 + so, Ap0 + k0);
            cp_async16(aDst1 + so, Ap1 + k0);
            cp_async16(bDst0 + so, Bp0 + k0);
            cp_async16(bDst1 + so, Bp1 + k0);
        }
        CP_COMMIT();
        CP_WAIT(STAGES - 1);
        __syncthreads();

        const char* Ab = smem + (s & (STAGES - 1)) * STAGE_B;
        const char* Bb = Ab + TILE_B;
#pragma unroll
        for (int kk = 0; kk < 2; kk++) {            // two k16 steps in BK=32
            const int kb = kk * 32 + t4 * 4;        // byte offset of k pair
            uint32_t a[4][4], b[4][2];
#pragma unroll
            for (int fm = 0; fm < 4; fm++) {
                const char* p0 = Ab + (wm * 64 + fm * 16 + g) * ROWB + kb;
                const char* p1 = p0 + 8 * ROWB;
                a[fm][0] = *(const uint32_t*)(p0);
                a[fm][1] = *(const uint32_t*)(p1);
                a[fm][2] = *(const uint32_t*)(p0 + 16);
                a[fm][3] = *(const uint32_t*)(p1 + 16);
            }
#pragma unroll
            for (int fn = 0; fn < 4; fn++) {
                const char* p = Bb + (wn * 32 + fn * 8 + g) * ROWB + kb;
                b[fn][0] = *(const uint32_t*)(p);
                b[fn][1] = *(const uint32_t*)(p + 16);
            }
#pragma unroll
            for (int fm = 0; fm < 4; fm++)
#pragma unroll
                for (int fn = 0; fn < 4; fn++)
                    mma_f16(acc[fm][fn], a[fm], b[fn]);
        }
        __syncthreads();
    }

    // epilogue: out = acc + wsum[row]*bias[col]; class-token rows (s==0) = 1.0
#pragma unroll
    for (int fm = 0; fm < 4; fm++) {
        const int row0 = m0 + wm * 64 + fm * 16 + g;
        const int row1 = row0 + 8;
        const bool ok0 = row0 < M_;
        const bool ok1 = row1 < M_;
        const bool cls0 = (row0 % S_) == 0;
        const bool cls1 = (row1 % S_) == 0;
        const float ws0 = ok0 ? wsum[row0] : 0.0f;
        const float ws1 = ok1 ? wsum[row1] : 0.0f;
#pragma unroll
        for (int fn = 0; fn < 4; fn++) {
            const int col = n0 + wn * 32 + fn * 8 + t4 * 2;
            const float b0 = bias[col];
            const float b1 = bias[col + 1];
            if (ok0) {
                float2 o;
                o.x = cls0 ? 1.0f : acc[fm][fn][0] + ws0 * b0;
                o.y = cls0 ? 1.0f : acc[fm][fn][1] + ws0 * b1;
                *(float2*)(C + (size_t)row0 * D_ + col) = o;
            }
            if (ok1) {
                float2 o;
                o.x = cls1 ? 1.0f : acc[fm][fn][2] + ws1 * b0;
                o.y = cls1 ? 1.0f : acc[fm][fn][3] + ws1 * b1;
                *(float2*)(C + (size_t)row1 * D_ + col) = o;
            }
        }
    }
}

// ---------------------------------------------------------------------------
// Inputs (metadata order): 0:x 1:img_ids 2:mask 3:Wq 4:bq 5:Wk 6:bk
//                          7:Wv 8:bv 9:avgs 10:std_devs 11:noise
// q/k/softmax are dead (softmax over singleton axis == 1): out = sampled v,
// and sampling commutes with the linear map -> gather x first, then one GEMM.
// ---------------------------------------------------------------------------
extern "C" void kernel_launch(void* const* d_in, const int* in_sizes, int n_in,
                              void* d_out, int out_size)
{
    const float* x       = (const float*)d_in[0];
    const int*   img_ids = (const int*)d_in[1];
    const float* Wv      = (const float*)d_in[7];
    const float* bv      = (const float*)d_in[8];
    const float* avgs    = (const float*)d_in[9];
    const float* stds    = (const float*)d_in[10];
    const float* noise   = (const float*)d_in[11];
    float* out = (float*)d_out;

    __half* xs = nullptr;
    __half* wt = nullptr;
    float*  ws = nullptr;
    cudaGetSymbolAddress((void**)&xs, g_xs);
    cudaGetSymbolAddress((void**)&wt, g_wt);
    cudaGetSymbolAddress((void**)&ws, g_ws);

    cudaFuncSetAttribute(gemm_f16, cudaFuncAttributeMaxDynamicSharedMemorySize,
                         SMEM_TOTAL);

    transpose_half<<<dim3(24, 24), dim3(32, 8)>>>(Wv, wt);
    gather_x<<<M_, 192>>>(x, img_ids, avgs, stds, noise, xs, ws);
    gemm_f16<<<dim3(6, 99), 256, SMEM_TOTAL>>>(xs, wt, bv, ws, out);
}